// round 16
// baseline (speedup 1.0000x reference)
#include <cuda_runtime.h>
#include <math.h>
#include <float.h>

// Problem geometry
#define NDIR   1986
#define NV     64
#define NBP    128     // B*P = 8*16
#define TPB    64      // 2 warps/block -> 28 blocks/SM -> one full wave
#define NCH    32      // 32 blocks x 64 dirs = 2048 >= 1986

// Output layout (float element offsets inside d_out)
#define OFF_POINTS 0
#define OFF_DH     762624
#define OFF_OVER   1779456
#define OFF_MEAN   1779584
#define OFF_DIRS   1779968
#define OFF_LV     1785926

__constant__ float c_pow10[21] = {
    1e0f, 1e1f, 1e2f, 1e3f, 1e4f, 1e5f, 1e6f, 1e7f, 1e8f, 1e9f, 1e10f,
    1e11f, 1e12f, 1e13f, 1e14f, 1e15f, 1e16f, 1e17f, 1e18f, 1e19f, 1e20f
};
__constant__ float c_rpow10[21] = {
    1e0f, 1e-1f, 1e-2f, 1e-3f, 1e-4f, 1e-5f, 1e-6f, 1e-7f, 1e-8f, 1e-9f, 1e-10f,
    1e-11f, 1e-12f, 1e-13f, 1e-14f, 1e-15f, 1e-16f, 1e-17f, 1e-18f, 1e-19f, 1e-20f
};

// f64->f32-cast trig at cancellation angles
#define COS_HALFPI  6.123234e-17f
#define SIN_NEGPI  -1.2246468e-16f

__device__ __forceinline__ float ex2f(float x) {
    float r;
    asm("ex2.approx.f32 %0, %1;" : "=f"(r) : "f"(x));
    return r;
}

__device__ __forceinline__ void make_dir(int d, float& dx, float& dy, float& dz) {
    const float STEP = 0.09817477042468103f;   // pi/32
    const float NPI  = -3.14159265358979323846f;
    const float NPI2 = -1.57079632679489662f;
    float c1, s1, c2, s2;
    if (d >= 1984) {
        c1 = COS_HALFPI;
        s1 = (d == 1984) ? -1.0f : 1.0f;
        c2 = -1.0f;
        s2 = SIN_NEGPI;
    } else {
        int i = (d >> 6) + 1;
        int j = d & 63;
        __sincosf(fmaf((float)i, STEP, NPI2), &s1, &c1);
        if (j == 0)       { c2 = -1.0f;       s2 = SIN_NEGPI; }
        else if (j == 16) { c2 = COS_HALFPI;  s2 = -1.0f; }
        else if (j == 48) { c2 = COS_HALFPI;  s2 = 1.0f; }
        else              { __sincosf(fmaf((float)j, STEP, NPI), &s2, &c2); }
    }
    dx = c1 * c2;
    dy = c1 * s2;
    dz = s1;
}

// ---------------------------------------------------------------------------
// Cold path (rare): exact reference semantics for one direction.
// ---------------------------------------------------------------------------
__device__ __noinline__ void cold_dir(const float4* slv, float p,
                                      float dx, float dy, float dz,
                                      float& h_out, float& rk_out,
                                      float& wx, float& wy, float& wz) {
    float zmax = 0.0f;
    for (int v = 0; v < NV; v++) {
        float4 lv = slv[v];
        float z = fmaf(lv.x, dx, fmaf(lv.y, dy, lv.z * dz));
        zmax = fmaxf(zmax, fmaxf(z, 0.0f));
    }
    if (!(zmax > 0.0f)) {
        float sx = 0.f, sy = 0.f, sz = 0.f;
        for (int v = 0; v < NV; v++) {
            float4 lv = slv[v];
            sx = fmaf(1e-20f, lv.x, sx);
            sy = fmaf(1e-20f, lv.y, sy);
            sz = fmaf(1e-20f, lv.z, sz);
        }
        wx = sx; wy = sy; wz = sz;
        h_out = 1e-20f; rk_out = 1e-20f;   // k = 1e20
        return;
    }
    float expo = log10f(zmax) * p;
    float lk   = (expo < -20.0f) ? ((-20.0f - expo) / p) : 0.0f;
    float ke   = fminf(fmaxf(ceilf(lk), 0.0f), 20.0f);
    int   kei  = (int)ke;
    float k    = c_pow10[kei];
    float sum = 0.0f;
    for (int v = 0; v < NV; v++) {
        float4 lv = slv[v];
        float z   = fmaf(lv.x, dx, fmaf(lv.y, dy, lv.z * dz));
        float zms = fmaxf(z, 0.0f) * k;
        if (zms > 0.0f) {
            float zp = exp2f(p * __log2f(zms));
            sum += fminf(fmaxf(zp, 1e-20f), 1e20f);
        }
    }
    float h = exp2f(__log2f(sum) * (1.0f / p));
    h = fminf(fmaxf(h, 1e-20f), 1e20f);
    float l2h = __log2f(h);
    float pm1 = p - 1.0f;
    float sx = 0.f, sy = 0.f, sz = 0.f;
    for (int v = 0; v < NV; v++) {
        float4 lv = slv[v];
        float z   = fmaf(lv.x, dx, fmaf(lv.y, dy, lv.z * dz));
        float zms = fmaxf(z, 0.0f) * k;
        float dh;
        if (zms > 0.0f) {
            float r = exp2f(pm1 * (__log2f(zms) - l2h));
            dh = fminf(fmaxf(r, 1e-20f), 1e20f);
        } else {
            dh = 1e-20f;
        }
        sx = fmaf(dh, lv.x, sx);
        sy = fmaf(dh, lv.y, sy);
        sz = fmaf(dh, lv.z, sz);
    }
    wx = sx; wy = sy; wz = sz;
    h_out = h; rk_out = c_rpow10[kei];
}

// ---------------------------------------------------------------------------
// Fused hot kernel: grid (32, 128) = 4096 blocks x 64 threads.
// 28 blocks/SM (regs capped at 36) -> 4144 slots >= 4096 -> ONE wave.
// ---------------------------------------------------------------------------
__global__ __launch_bounds__(TPB, 28)
void fused_kernel(const float* __restrict__ verts,
                  const float* __restrict__ smooth,
                  float* __restrict__ out) {
    __shared__ float4 slv[NV];
    __shared__ float  sred[6];
    __shared__ float  smean[3];

    const int bp  = blockIdx.y;
    const int tid = threadIdx.x;             // 0..63 == vertex index
    const int d   = blockIdx.x * TPB + tid;

    // ---- prologue: mean + local_v (tid < NV always) ----
    const float* vp = verts + (bp * NV + tid) * 3;
    float px = vp[0], py = vp[1], pz = vp[2];
    {
        float sx = px, sy = py, sz = pz;
        #pragma unroll
        for (int o = 16; o > 0; o >>= 1) {
            sx += __shfl_down_sync(0xffffffffu, sx, o);
            sy += __shfl_down_sync(0xffffffffu, sy, o);
            sz += __shfl_down_sync(0xffffffffu, sz, o);
        }
        int warp = tid >> 5, lane = tid & 31;
        if (lane == 0) {
            sred[warp * 3 + 0] = sx;
            sred[warp * 3 + 1] = sy;
            sred[warp * 3 + 2] = sz;
        }
    }
    __syncthreads();
    if (tid == 0) {
        smean[0] = (sred[0] + sred[3]) * (1.0f / 64.0f);
        smean[1] = (sred[1] + sred[4]) * (1.0f / 64.0f);
        smean[2] = (sred[2] + sred[5]) * (1.0f / 64.0f);
    }
    __syncthreads();
    const float mx = smean[0], my = smean[1], mz = smean[2];
    slv[tid] = make_float4(px - mx, py - my, pz - mz, 0.0f);
    __syncthreads();

    // ---- aux per-bp outputs ----
    if (blockIdx.x == 0) {
        if (tid == 0) {
            out[OFF_MEAN + bp * 3 + 0] = mx;
            out[OFF_MEAN + bp * 3 + 1] = my;
            out[OFF_MEAN + bp * 3 + 2] = mz;
            out[OFF_OVER + bp] = 0.0f;
        }
        float4 lv = slv[tid];
        int idx = OFF_LV + (bp * NV + tid) * 3;
        out[idx + 0] = lv.x;
        out[idx + 1] = lv.y;
        out[idx + 2] = lv.z;
    }

    if (d >= NDIR) return;   // no barriers below

    // ---- direction ----
    float ax, ay, az;
    make_dir(d, ax, ay, az);

    if (blockIdx.y == 0) {
        out[OFF_DIRS + 3 * d + 0] = ax;
        out[OFF_DIRS + 3 * d + 1] = ay;
        out[OFF_DIRS + 3 * d + 2] = az;
    }

    const float p   = __ldg(&smooth[bp]);
    const float pm1 = p - 1.0f;

    // ---- lean fused loop ----
    float wx = 0.f, wy = 0.f, wz = 0.f;

    #pragma unroll 8
    for (int v = 0; v < NV; v++) {
        float4 lv = slv[v];
        float z  = fmaf(lv.x, ax, fmaf(lv.y, ay, lv.z * az));
        float zm = fmaxf(z, 0.0f);
        float w  = ex2f(pm1 * __log2f(zm));    // zm^(p-1); 0 when zm==0
        wx = fmaf(w, lv.x, wx);
        wy = fmaf(w, lv.y, wy);
        wz = fmaf(w, lv.z, wz);
    }

    const float invp = 1.0f / p;
    const float iomp = invp - 1.0f;              // (1-p)/p

    // ---- epilogue ----
    float s = fmaf(ax, wx, fmaf(ay, wy, az * wz));
    float h, rk = 1.0f, scale;
    if (s > 1e-6f) {                             // hot: floors/k invisible
        float ls = __log2f(s);
        h = fminf(ex2f(ls * invp), 1e20f);
        scale = ex2f(ls * iomp);                 // h^(1-p)
    } else {                                     // rare: exact replay
        cold_dir(slv, p, ax, ay, az, h, rk, wx, wy, wz);
        scale = 1.0f;
    }
    size_t pidx = ((size_t)bp * NDIR + d) * 3;
    out[OFF_POINTS + pidx + 0] = fmaf(wx, scale, mx);
    out[OFF_POINTS + pidx + 1] = fmaf(wy, scale, my);
    out[OFF_POINTS + pidx + 2] = fmaf(wz, scale, mz);
    ((float4*)(out + OFF_DH))[(size_t)bp * NDIR + d] =
        make_float4(ax, ay, az, h * rk);
}

// ---------------------------------------------------------------------------
extern "C" void kernel_launch(void* const* d_in, const int* in_sizes, int n_in,
                              void* d_out, int out_size) {
    const float* verts  = (const float*)d_in[0];
    const float* smooth = (const float*)d_in[1];
    float* out = (float*)d_out;

    fused_kernel<<<dim3(NCH, NBP), TPB>>>(verts, smooth, out);
}

// round 17
// speedup vs baseline: 1.3145x; 1.3145x over previous
#include <cuda_runtime.h>
#include <math.h>
#include <float.h>

// Problem geometry
#define NDIR   1986
#define NV     64
#define NBP    128     // B*P = 8*16
#define TPB    64
#define NCH    16      // 16 x 64 = 1024 threads >= 993 antipodal pairs
#define NPAIR  993

// Output layout (float element offsets inside d_out)
#define OFF_POINTS 0
#define OFF_DH     762624
#define OFF_OVER   1779456
#define OFF_MEAN   1779584
#define OFF_DIRS   1779968
#define OFF_LV     1785926

__constant__ float c_pow10[21] = {
    1e0f, 1e1f, 1e2f, 1e3f, 1e4f, 1e5f, 1e6f, 1e7f, 1e8f, 1e9f, 1e10f,
    1e11f, 1e12f, 1e13f, 1e14f, 1e15f, 1e16f, 1e17f, 1e18f, 1e19f, 1e20f
};
__constant__ float c_rpow10[21] = {
    1e0f, 1e-1f, 1e-2f, 1e-3f, 1e-4f, 1e-5f, 1e-6f, 1e-7f, 1e-8f, 1e-9f, 1e-10f,
    1e-11f, 1e-12f, 1e-13f, 1e-14f, 1e-15f, 1e-16f, 1e-17f, 1e-18f, 1e-19f, 1e-20f
};

// f64->f32-cast trig at cancellation angles
#define COS_HALFPI  6.123234e-17f
#define SIN_NEGPI  -1.2246468e-16f

__device__ __forceinline__ float ex2f(float x) {
    float r;
    asm("ex2.approx.f32 %0, %1;" : "=f"(r) : "f"(x));
    return r;
}

__device__ __forceinline__ void make_dir(int d, float& dx, float& dy, float& dz) {
    const float STEP = 0.09817477042468103f;   // pi/32
    const float NPI  = -3.14159265358979323846f;
    const float NPI2 = -1.57079632679489662f;
    float c1, s1, c2, s2;
    if (d >= 1984) {
        c1 = COS_HALFPI;
        s1 = (d == 1984) ? -1.0f : 1.0f;
        c2 = -1.0f;
        s2 = SIN_NEGPI;
    } else {
        int i = (d >> 6) + 1;
        int j = d & 63;
        __sincosf(fmaf((float)i, STEP, NPI2), &s1, &c1);
        if (j == 0)       { c2 = -1.0f;       s2 = SIN_NEGPI; }
        else if (j == 16) { c2 = COS_HALFPI;  s2 = -1.0f; }
        else if (j == 48) { c2 = COS_HALFPI;  s2 = 1.0f; }
        else              { __sincosf(fmaf((float)j, STEP, NPI), &s2, &c2); }
    }
    dx = c1 * c2;
    dy = c1 * s2;
    dz = s1;
}

// ---------------------------------------------------------------------------
// Cold path (rare): exact reference semantics for one direction.
// ---------------------------------------------------------------------------
__device__ __noinline__ void cold_dir(const float4* slv, float p,
                                      float dx, float dy, float dz,
                                      float& h_out, float& rk_out,
                                      float& wx, float& wy, float& wz) {
    float zmax = 0.0f;
    for (int v = 0; v < NV; v++) {
        float4 lv = slv[v];
        float z = fmaf(lv.x, dx, fmaf(lv.y, dy, lv.z * dz));
        zmax = fmaxf(zmax, fmaxf(z, 0.0f));
    }
    if (!(zmax > 0.0f)) {
        float sx = 0.f, sy = 0.f, sz = 0.f;
        for (int v = 0; v < NV; v++) {
            float4 lv = slv[v];
            sx = fmaf(1e-20f, lv.x, sx);
            sy = fmaf(1e-20f, lv.y, sy);
            sz = fmaf(1e-20f, lv.z, sz);
        }
        wx = sx; wy = sy; wz = sz;
        h_out = 1e-20f; rk_out = 1e-20f;   // k = 1e20
        return;
    }
    float expo = log10f(zmax) * p;
    float lk   = (expo < -20.0f) ? ((-20.0f - expo) / p) : 0.0f;
    float ke   = fminf(fmaxf(ceilf(lk), 0.0f), 20.0f);
    int   kei  = (int)ke;
    float k    = c_pow10[kei];
    float sum = 0.0f;
    for (int v = 0; v < NV; v++) {
        float4 lv = slv[v];
        float z   = fmaf(lv.x, dx, fmaf(lv.y, dy, lv.z * dz));
        float zms = fmaxf(z, 0.0f) * k;
        if (zms > 0.0f) {
            float zp = exp2f(p * __log2f(zms));
            sum += fminf(fmaxf(zp, 1e-20f), 1e20f);
        }
    }
    float h = exp2f(__log2f(sum) * (1.0f / p));
    h = fminf(fmaxf(h, 1e-20f), 1e20f);
    float l2h = __log2f(h);
    float pm1 = p - 1.0f;
    float sx = 0.f, sy = 0.f, sz = 0.f;
    for (int v = 0; v < NV; v++) {
        float4 lv = slv[v];
        float z   = fmaf(lv.x, dx, fmaf(lv.y, dy, lv.z * dz));
        float zms = fmaxf(z, 0.0f) * k;
        float dh;
        if (zms > 0.0f) {
            float r = exp2f(pm1 * (__log2f(zms) - l2h));
            dh = fminf(fmaxf(r, 1e-20f), 1e20f);
        } else {
            dh = 1e-20f;
        }
        sx = fmaf(dh, lv.x, sx);
        sy = fmaf(dh, lv.y, sy);
        sz = fmaf(dh, lv.z, sz);
    }
    wx = sx; wy = sy; wz = sz;
    h_out = h; rk_out = c_rpow10[kei];
}

// ---------------------------------------------------------------------------
// Per-direction epilogue: reconstruct sum, compute h/scale (or cold replay),
// write points + direction_h.
// ---------------------------------------------------------------------------
__device__ __forceinline__ void finish_dir(const float4* slv, float p,
                                           float invp, float iomp,
                                           float dx, float dy, float dz,
                                           float wx, float wy, float wz,
                                           float mx, float my, float mz,
                                           int bp, int d,
                                           float* __restrict__ out) {
    float s = fmaf(dx, wx, fmaf(dy, wy, dz * wz));   // == sum of zm^p
    float h, rk = 1.0f, scale;
    if (s > 1e-6f) {                                 // hot: floors/k invisible
        float ls = __log2f(s);
        h = fminf(ex2f(ls * invp), 1e20f);
        scale = ex2f(ls * iomp);                     // h^(1-p)
    } else {                                         // rare: exact replay
        cold_dir(slv, p, dx, dy, dz, h, rk, wx, wy, wz);
        scale = 1.0f;
    }
    size_t pidx = ((size_t)bp * NDIR + d) * 3;
    out[OFF_POINTS + pidx + 0] = fmaf(wx, scale, mx);
    out[OFF_POINTS + pidx + 1] = fmaf(wy, scale, my);
    out[OFF_POINTS + pidx + 2] = fmaf(wz, scale, mz);
    ((float4*)(out + OFF_DH))[(size_t)bp * NDIR + d] =
        make_float4(dx, dy, dz, h * rk);
}

// ---------------------------------------------------------------------------
// Fused antipodal-pair kernel: grid (NCH, NBP) = 2048 blocks x 64 threads.
// One thread = one antipodal direction pair (993 pairs cover all 1986 dirs).
// z' = -z for the antipode, so one dot + one LG2/EX2 chain serves both dirs;
// the weight routes to the accumulator set matching sign(z).
// ---------------------------------------------------------------------------
__global__ __launch_bounds__(TPB)
void fused_kernel(const float* __restrict__ verts,
                  const float* __restrict__ smooth,
                  float* __restrict__ out) {
    __shared__ float4 slv[NV];
    __shared__ float  sred[6];
    __shared__ float  smean[3];

    const int bp  = blockIdx.y;
    const int tid = threadIdx.x;             // 0..63 == vertex index
    const int t   = blockIdx.x * TPB + tid;  // pair index

    // ---- prologue: mean + local_v ----
    const float* vp = verts + (bp * NV + tid) * 3;
    float px = vp[0], py = vp[1], pz = vp[2];
    {
        float sx = px, sy = py, sz = pz;
        #pragma unroll
        for (int o = 16; o > 0; o >>= 1) {
            sx += __shfl_down_sync(0xffffffffu, sx, o);
            sy += __shfl_down_sync(0xffffffffu, sy, o);
            sz += __shfl_down_sync(0xffffffffu, sz, o);
        }
        int warp = tid >> 5, lane = tid & 31;
        if (lane == 0) {
            sred[warp * 3 + 0] = sx;
            sred[warp * 3 + 1] = sy;
            sred[warp * 3 + 2] = sz;
        }
    }
    __syncthreads();
    if (tid == 0) {
        smean[0] = (sred[0] + sred[3]) * (1.0f / 64.0f);
        smean[1] = (sred[1] + sred[4]) * (1.0f / 64.0f);
        smean[2] = (sred[2] + sred[5]) * (1.0f / 64.0f);
    }
    __syncthreads();
    const float mx = smean[0], my = smean[1], mz = smean[2];
    slv[tid] = make_float4(px - mx, py - my, pz - mz, 0.0f);
    __syncthreads();

    // ---- aux per-bp outputs ----
    if (blockIdx.x == 0) {
        if (tid == 0) {
            out[OFF_MEAN + bp * 3 + 0] = mx;
            out[OFF_MEAN + bp * 3 + 1] = my;
            out[OFF_MEAN + bp * 3 + 2] = mz;
            out[OFF_OVER + bp] = 0.0f;
        }
        float4 lv = slv[tid];
        int idx = OFF_LV + (bp * NV + tid) * 3;
        out[idx + 0] = lv.x;
        out[idx + 1] = lv.y;
        out[idx + 2] = lv.z;
    }

    if (t >= NPAIR) return;   // no barriers below

    // ---- pair index -> (d, dp) ----
    int d, dp;
    if (t < 960) {
        int i = (t >> 6) + 1;
        int j = t & 63;
        d  = t;
        dp = (31 - i) * 64 + ((j + 32) & 63);   // antipode (32-i, j+32)
    } else if (t < 992) {
        d  = t;                                  // i = 16, j = t-960 < 32
        dp = t + 32;                             // (16, j+32)
    } else {
        d  = 1984;
        dp = 1985;
    }

    // ---- representative dir; antipode = exact negation (poles special) ----
    float ax, ay, az;
    make_dir(d, ax, ay, az);
    float bx = -ax, by = -ay, bz = -az;
    if (t == 992) make_dir(1985, bx, by, bz);   // pole dx,dy not exact negations

    if (blockIdx.y == 0) {
        out[OFF_DIRS + 3 * d  + 0] = ax;
        out[OFF_DIRS + 3 * d  + 1] = ay;
        out[OFF_DIRS + 3 * d  + 2] = az;
        out[OFF_DIRS + 3 * dp + 0] = bx;
        out[OFF_DIRS + 3 * dp + 1] = by;
        out[OFF_DIRS + 3 * dp + 2] = bz;
    }

    const float p   = __ldg(&smooth[bp]);
    const float pm1 = p - 1.0f;

    // ---- fused pair loop: one MUFU chain serves both directions ----
    float wxp = 0.f, wyp = 0.f, wzp = 0.f;   // dir a (z > 0 side)
    float wxn = 0.f, wyn = 0.f, wzn = 0.f;   // dir b (z < 0 side)

    #pragma unroll 8
    for (int v = 0; v < NV; v++) {
        float4 lv = slv[v];
        float z  = fmaf(lv.x, ax, fmaf(lv.y, ay, lv.z * az));
        float w  = ex2f(pm1 * __log2f(fabsf(z)));   // |z|^(p-1); 0 when z==0
        float wp = (z > 0.0f) ? w : 0.0f;
        float wn = w - wp;
        wxp = fmaf(wp, lv.x, wxp);
        wyp = fmaf(wp, lv.y, wyp);
        wzp = fmaf(wp, lv.z, wzp);
        wxn = fmaf(wn, lv.x, wxn);
        wyn = fmaf(wn, lv.y, wyn);
        wzn = fmaf(wn, lv.z, wzn);
    }

    const float invp = 1.0f / p;
    const float iomp = invp - 1.0f;              // (1-p)/p

    finish_dir(slv, p, invp, iomp, ax, ay, az, wxp, wyp, wzp,
               mx, my, mz, bp, d, out);
    finish_dir(slv, p, invp, iomp, bx, by, bz, wxn, wyn, wzn,
               mx, my, mz, bp, dp, out);
}

// ---------------------------------------------------------------------------
extern "C" void kernel_launch(void* const* d_in, const int* in_sizes, int n_in,
                              void* d_out, int out_size) {
    const float* verts  = (const float*)d_in[0];
    const float* smooth = (const float*)d_in[1];
    float* out = (float*)d_out;

    fused_kernel<<<dim3(NCH, NBP), TPB>>>(verts, smooth, out);
}